// round 13
// baseline (speedup 1.0000x reference)
#include <cuda_runtime.h>

// out[b, s, d] = in[b, s, d] + PE[s, d]
// PE[s, 2i]   = sin(s / 10000^(2i/1024)),  PE[s, 2i+1] = cos(...)
//
// B=8, S=4096, D=1024, fp32 — 268 MB pure stream, DRAM-bound (~75%).
// R13: decouple CTA size from per-thread work. Per-thread optimum is
// 2 batches (R11 showed 1 batch/thread breaks amortization); CTA-quantum
// shrinking is what pays (R9/R10). So: 128-thread CTAs covering HALF a
// PE row, still 2 batches/thread, 16 CTAs/SM, 32768 CTAs total — drain
// quantum halves again without touching the per-thread pipeline.
// fast_sincos: Cody-Waite 2-term mod 2pi + __sincosf (validated: rel_err
// identical to accurate sincosf at 1.898e-5).
// Rejected: L2 policy pinning (R3-5), 256-bit ops (R6), persistent (R7),
// 1 batch/thread (R11).

#define SEQ_LEN 4096
#define D_MODEL 1024
#define BATCH   8
#define BSPLIT  4                      // batch quarters per position
#define BPER    (BATCH / BSPLIT)       // 2 batches per thread
#define THREADS 128                    // half a row: 128 x float4 = 512 floats
#define RSPLIT  2                      // row halves per position

__device__ __forceinline__ void fast_sincos(float ang, float* s, float* c) {
    // 2-term Cody-Waite: 2pi = HI + MID, HI exact in fp32.
    const float INV_2PI = 0.15915494309189535f;
    const float HI = 6.28125f;                 // exact
    const float MID = 1.9353071795864769e-3f;  // 2pi - HI
    float k = rintf(ang * INV_2PI);
    float r = fmaf(k, -HI, ang);
    r = fmaf(k, -MID, r);
    __sincosf(r, s, c);                        // |r| <= pi: MUFU-accurate
}

__global__ void __launch_bounds__(THREADS, 16)
pe_add_kernel(const float4* __restrict__ in, float4* __restrict__ out) {
    const int pos   = blockIdx.x;              // sequence position 0..4095
    const int bseg  = blockIdx.y;              // batch segment 0..3
    const int rhalf = blockIdx.z;              // row half 0..1
    const int t     = rhalf * THREADS + threadIdx.x;  // float4 idx in row 0..255

    // 32-bit element offsets in float4 units.
    const int row_f4       = D_MODEL / 4;            // 256
    const int batch_stride = SEQ_LEN * row_f4;       // 1,048,576
    int idx = (bseg * BPER) * batch_stride + pos * row_f4 + t;

    // Kick the first load before the trig prologue.
    float4 cur = __ldcs(in + idx);

    // PE for this thread's float4 (dims 4t..4t+3), computed once, reused 2x.
    const float LOG2_10000 = 13.287712379549449f;
    const float fpos = (float)pos;

    float e0 = (float)(4 * t)     * (1.0f / 1024.0f);
    float e1 = (float)(4 * t + 2) * (1.0f / 1024.0f);
    float a0 = fpos / exp2f(e0 * LOG2_10000);
    float a1 = fpos / exp2f(e1 * LOG2_10000);

    float s0, c0, s1, c1;
    fast_sincos(a0, &s0, &c0);
    fast_sincos(a1, &s1, &c1);

    const float4 pe = make_float4(s0, c0, s1, c1);

    // 2-deep pipeline over this thread's 2 batches.
#pragma unroll
    for (int b = 0; b < BPER; ++b) {
        int next_idx = idx + batch_stride;
        float4 nxt;
        if (b < BPER - 1) nxt = __ldcs(in + next_idx);
        float4 v = cur;
        v.x += pe.x;
        v.y += pe.y;
        v.z += pe.z;
        v.w += pe.w;
        __stcs(out + idx, v);
        cur = nxt;
        idx = next_idx;
    }
}

extern "C" void kernel_launch(void* const* d_in, const int* in_sizes, int n_in,
                              void* d_out, int out_size) {
    const float4* in  = (const float4*)d_in[0];
    float4*       out = (float4*)d_out;
    dim3 grid(SEQ_LEN, BSPLIT, RSPLIT);
    pe_add_kernel<<<grid, THREADS>>>(in, out);
}

// round 14
// speedup vs baseline: 1.0383x; 1.0383x over previous
#include <cuda_runtime.h>

// out[b, s, d] = in[b, s, d] + PE[s, d]
// PE[s, 2i]   = sin(s / 10000^(2i/1024)),  PE[s, 2i+1] = cos(...)
//
// B=8, S=4096, D=1024, fp32 — 268 MB pure stream. FINAL (R12 form).
// Best profiled: 36.00us kernel, DRAM 75.4% (5.97 TB/s) vs 33.5us floor
// at 100% of 8TB/s spec — at the mixed-R/W HBM roofline.
//
// Design: grid (4096 pos, 4 batch-segments), 256 threads x float4 = one
// PE row; each thread computes its 2 sin/cos pairs once (Cody-Waite
// reduction + __sincosf) and streams 2 batch copies with a 2-deep load
// pipeline, streaming ld/st hints, 32-bit indexing.
//
// Measured design space (wall us): batches/CTA 8:45.1 | 4:44.3 |
// 2(256thr):43.5 | 2(128thr):45.2 | 1:45.8 -> optimum 2 b/CTA x 256 thr.
// Rejected: L2 evict policy pinning (inert), 256-bit v8 ops (-12%),
// persistent single-wave grid (-25%), accurate sincosf (equal, costlier).

#define SEQ_LEN 4096
#define D_MODEL 1024
#define BATCH   8
#define BSPLIT  4                      // batch quarters per position
#define BPER    (BATCH / BSPLIT)       // 2 batches per CTA
#define THREADS 256                    // 256 x float4 = one PE row

__device__ __forceinline__ void fast_sincos(float ang, float* s, float* c) {
    // 2-term Cody-Waite: 2pi = HI + MID, HI exact in fp32.
    // k <= 652 here -> reduction error ~7e-8; __sincosf on [-pi,pi] ~4e-7.
    const float INV_2PI = 0.15915494309189535f;
    const float HI = 6.28125f;                 // exact
    const float MID = 1.9353071795864769e-3f;  // 2pi - HI
    float k = rintf(ang * INV_2PI);
    float r = fmaf(k, -HI, ang);
    r = fmaf(k, -MID, r);
    __sincosf(r, s, c);
}

__global__ void __launch_bounds__(THREADS, 8)
pe_add_kernel(const float4* __restrict__ in, float4* __restrict__ out) {
    const int pos  = blockIdx.x;       // sequence position 0..4095
    const int bseg = blockIdx.y;       // batch segment 0..3
    const int t    = threadIdx.x;      // float4 index within row 0..255

    // 32-bit element offsets in float4 units.
    const int row_f4       = D_MODEL / 4;            // 256
    const int batch_stride = SEQ_LEN * row_f4;       // 1,048,576
    int idx = (bseg * BPER) * batch_stride + pos * row_f4 + t;

    // Kick the first load before the trig prologue.
    float4 cur = __ldcs(in + idx);

    // PE for this thread's float4 (dims 4t..4t+3), computed once, reused 2x.
    const float LOG2_10000 = 13.287712379549449f;
    const float fpos = (float)pos;

    float e0 = (float)(4 * t)     * (1.0f / 1024.0f);
    float e1 = (float)(4 * t + 2) * (1.0f / 1024.0f);
    float a0 = fpos / exp2f(e0 * LOG2_10000);
    float a1 = fpos / exp2f(e1 * LOG2_10000);

    float s0, c0, s1, c1;
    fast_sincos(a0, &s0, &c0);
    fast_sincos(a1, &s1, &c1);

    const float4 pe = make_float4(s0, c0, s1, c1);

    // 2-deep pipeline over this CTA's 2 batches.
#pragma unroll
    for (int b = 0; b < BPER; ++b) {
        int next_idx = idx + batch_stride;
        float4 nxt;
        if (b < BPER - 1) nxt = __ldcs(in + next_idx);
        float4 v = cur;
        v.x += pe.x;
        v.y += pe.y;
        v.z += pe.z;
        v.w += pe.w;
        __stcs(out + idx, v);
        cur = nxt;
        idx = next_idx;
    }
}

extern "C" void kernel_launch(void* const* d_in, const int* in_sizes, int n_in,
                              void* d_out, int out_size) {
    const float4* in  = (const float4*)d_in[0];
    float4*       out = (float4*)d_out;
    dim3 grid(SEQ_LEN, BSPLIT);
    pe_add_kernel<<<grid, THREADS>>>(in, out);
}